// round 16
// baseline (speedup 1.0000x reference)
#include <cuda_runtime.h>
#include <cstdint>

#define B_  8
#define H_  224
#define W_  224
#define C_  192
#define QT  8        // q positions per block
#define NQ  2        // q per thread
#define PAIRS 32     // channel pairs (threadIdx.x)
#define QTH  4       // q-thread groups (threadIdx.y)
#define NTHREADS 128
#define RH  56       // output rows per block
#define SROW 14      // staged columns per row (QT + 6)
#define STAGES 8     // stages 0..6: ring (t mod 7); stage 7: row 61 only
#define STAGE_BYTES (SROW * 64 * 4)          // 3584 B per stage
#define ROWSZ (W_ * C_)
#define IMGSZ (H_ * W_ * C_)

typedef unsigned long long u64;

__device__ __forceinline__ void fma2(u64 &d, u64 a, u64 b) {
    asm("fma.rn.f32x2 %0, %1, %2, %0;" : "+l"(d) : "l"(a), "l"(b));
}
__device__ __forceinline__ void mul2(u64 &d, u64 a, u64 b) {
    asm("mul.rn.f32x2 %0, %1, %2;" : "=l"(d) : "l"(a), "l"(b));
}
__device__ __forceinline__ void cpasync16(uint32_t dst, const float* src) {
    asm volatile("cp.async.cg.shared.global [%0], [%1], 16;" :: "r"(dst), "l"(src));
}
__device__ __forceinline__ void cp_commit() {
    asm volatile("cp.async.commit_group;" ::: "memory");
}
#define CP_WAIT(N) asm volatile("cp.async.wait_group %0;" :: "n"(N) : "memory")
__device__ __forceinline__ uint32_t smem_u32(const void* p) {
    uint32_t a;
    asm("{ .reg .u64 t; cvta.to.shared.u64 t, %1; cvt.u32.u64 %0, t; }" : "=r"(a) : "l"(p));
    return a;
}

// Compute one row-step at phase T7 = t % 7, consuming COMPILE-TIME stage CS.
// Kernel rows i in [ILO, IHI] only (wedge pruning).
// i == 6 is the FIRST contribution to the fresh slot (T7+1)%7 and is emitted
// as an overwriting MUL (no zeroing ever needed). Slot (T7+2)%7 completes
// with i == 0 and is stored (if DOSTORE).
#define STEP_C(T7, ILO, IHI, CS, DOSTORE) do {                                \
    const char* sb = (const char*)sbuf + (CS) * STAGE_BYTES                   \
                     + ty * (NQ * 256) + tx * 8;                              \
    u64 w[8];                                                                 \
    _Pragma("unroll")                                                         \
    for (int d = 0; d < 8; ++d)                                               \
        w[d] = *(const u64*)(sb + d * 256);                                   \
    _Pragma("unroll")                                                         \
    for (int i = 0; i < 7; ++i) {                                             \
        if (i >= (ILO) && i <= (IHI)) {                                       \
            const int s = ((T7) + i + 2) % 7;                                 \
            if (i == 6) {                                                     \
                mul2(acc[s][0], kreg[6 * 7 + 0], w[6]);                       \
                mul2(acc[s][1], kreg[6 * 7 + 0], w[7]);                       \
                _Pragma("unroll")                                             \
                for (int j = 1; j < 7; ++j) {                                 \
                    const u64 kv = kreg[6 * 7 + j];                           \
                    fma2(acc[s][0], kv, w[6 - j]);                            \
                    fma2(acc[s][1], kv, w[7 - j]);                            \
                }                                                             \
            } else {                                                          \
                _Pragma("unroll")                                             \
                for (int j = 0; j < 7; ++j) {                                 \
                    const u64 kv = kreg[i * 7 + j];                           \
                    fma2(acc[s][0], kv, w[6 - j]);                            \
                    fma2(acc[s][1], kv, w[7 - j]);                            \
                }                                                             \
            }                                                                 \
        }                                                                     \
    }                                                                         \
    if (DOSTORE) {                                                            \
        const int so = ((T7) + 2) % 7;                                        \
        *(u64*)(out + outOff)      = acc[so][0];                              \
        *(u64*)(out + outOff + C_) = acc[so][1];                              \
        outOff += ROWSZ;                                                      \
    }                                                                         \
} while (0)

// Macro for rows t=2m, 2m+1 (phases T7a=(2m)%7, T7b=(2m+1)%7; consume stages
// == phases). Prefetch rows 2m+5, 2m+6 into stages PA=(T7a+5)%7, PB=(T7a+6)%7
// -- the stages of rows 2m-2, 2m-1, consumed last macro; the barrier orders
// all warps' reads before these writes. WN: #groups left pending after wait.
#define MACRO7(T7a, LOa, Sa, T7b, LOb, Sb, PA, PB, WN) do {                   \
    CP_WAIT(WN);                                                              \
    __syncthreads();                                                          \
    {                                                                         \
        const uint32_t dA = sdst + (PA) * STAGE_BYTES;                        \
        cpasync16(dA, rowPtr + colOff0);                                      \
        if (has1) cpasync16(dA + 2048, rowPtr + colOff1);                     \
        rowPtr += ROWSZ; if (rowPtr >= xEnd) rowPtr -= IMGSZ;                 \
        const uint32_t dB = sdst + (PB) * STAGE_BYTES;                        \
        cpasync16(dB, rowPtr + colOff0);                                      \
        if (has1) cpasync16(dB + 2048, rowPtr + colOff1);                     \
        rowPtr += ROWSZ; if (rowPtr >= xEnd) rowPtr -= IMGSZ;                 \
        cp_commit();                                                          \
    }                                                                         \
    STEP_C(T7a, LOa, 6, T7a, Sa);                                             \
    STEP_C(T7b, LOb, 6, T7b, Sb);                                             \
} while (0)

// 7-macro group (14 rows): phase pattern repeats exactly. All stage indices
// compile-time; body ~27KB -> L1.5 I$ resident.
#define GROUP7C()                                                             \
    MACRO7(0, 0, 1,  1, 0, 1,  5, 6, 1);                                      \
    MACRO7(2, 0, 1,  3, 0, 1,  0, 1, 1);                                      \
    MACRO7(4, 0, 1,  5, 0, 1,  2, 3, 1);                                      \
    MACRO7(6, 0, 1,  0, 0, 1,  4, 5, 1);                                      \
    MACRO7(1, 0, 1,  2, 0, 1,  6, 0, 1);                                      \
    MACRO7(3, 0, 1,  4, 0, 1,  1, 2, 1);                                      \
    MACRO7(5, 0, 1,  6, 0, 1,  3, 4, 1)

__global__ void __launch_bounds__(NTHREADS, 3)
dwconv_pipe11(const float* __restrict__ x, const float* __restrict__ kern,
              float* __restrict__ out)
{
    __shared__ float sbuf[STAGES][SROW][64];   // 28,672 B (7-ring + row-61 slot)
    __shared__ float swt[49][64];              // 12,544 B weight transpose buf

    const int tx  = threadIdx.x;           // channel pair 0..31
    const int ty  = threadIdx.y;           // q group 0..3
    const int tid = ty * PAIRS + tx;

    const int wt = blockIdx.x;              // 0..27
    const int ht = blockIdx.y;              // 0..3
    const int bz = blockIdx.z;              // 0..23
    const int b  = bz / 3;
    const int g  = bz % 3;

    const int qbase = wt * QT;
    const int p0    = ht * RH;              // p0 % 7 == 0
    const int cbase = g * 64;
    const int c0    = cbase + 2 * tx;

    // ---- cp.async staging plan: 224 float4 per stage, threads 0..95 take 2 ----
    const int s0 = tid >> 4, v0 = tid & 15;             // cols 0..7
    const bool has1 = tid < 96;
    const int s1 = (tid + 128) >> 4;                    // cols 8..13
    int qg0 = qbase - 3 + s0; qg0 += (qg0 < 0) ? W_ : 0; qg0 -= (qg0 >= W_) ? W_ : 0;
    int qg1 = qbase - 3 + s1; qg1 += (qg1 < 0) ? W_ : 0; qg1 -= (qg1 >= W_) ? W_ : 0;
    const int colOff0 = qg0 * C_ + cbase + v0 * 4;
    const int colOff1 = qg1 * C_ + cbase + v0 * 4;
    const uint32_t sdst = smem_u32(&sbuf[0][0][0]) + (uint32_t)(s0 * 256 + v0 * 16);

    // row cursor (circular over H, pointer-only)
    const float* const xBase = x + b * IMGSZ;
    const float* const xEnd  = xBase + IMGSZ;
    const float* rowPtr = xBase + (p0 - 3 < 0 ? p0 - 3 + H_ : p0 - 3) * ROWSZ;

    // ---- prologue cp.asyncs FIRST (overlap with weight load below) ----
    // Gp0: rows 0,1 -> stages 0,1 ; Gp1: rows 2,3 -> stages 2,3 ;
    // Gp2: row 4 -> stage 4 AND row 61 -> dedicated stage 7.
    #pragma unroll
    for (int pr = 0; pr < 2; ++pr) {
        uint32_t dA = sdst + (2 * pr) * STAGE_BYTES;
        cpasync16(dA, rowPtr + colOff0);
        if (has1) cpasync16(dA + 2048, rowPtr + colOff1);
        rowPtr += ROWSZ; if (rowPtr >= xEnd) rowPtr -= IMGSZ;
        uint32_t dB = sdst + (2 * pr + 1) * STAGE_BYTES;
        cpasync16(dB, rowPtr + colOff0);
        if (has1) cpasync16(dB + 2048, rowPtr + colOff1);
        rowPtr += ROWSZ; if (rowPtr >= xEnd) rowPtr -= IMGSZ;
        cp_commit();
    }
    {
        uint32_t dA = sdst + 4 * STAGE_BYTES;
        cpasync16(dA, rowPtr + colOff0);
        if (has1) cpasync16(dA + 2048, rowPtr + colOff1);
        rowPtr += ROWSZ; if (rowPtr >= xEnd) rowPtr -= IMGSZ;
        int r61 = p0 + 58; if (r61 >= H_) r61 -= H_;     // input row of step 61
        const float* p61 = xBase + r61 * ROWSZ;
        uint32_t dB = sdst + 7 * STAGE_BYTES;
        cpasync16(dB, p61 + colOff0);
        if (has1) cpasync16(dB + 2048, p61 + colOff1);
        cp_commit();
    }

    // ---- weight load (overlapped): coalesced LDG -> transpose -> LDS.64 ----
    u64 kreg[49];
    {
        const float4* kslab = (const float4*)(kern + cbase * 49);  // 16B-aligned
        #pragma unroll
        for (int i = tid; i < 784; i += NTHREADS) {
            const float4 v = kslab[i];
            const int base = i * 4;             // = c*49 + t
            #pragma unroll
            for (int e = 0; e < 4; ++e) {
                const int idx = base + e;
                const int c = idx / 49;
                const int t = idx - c * 49;
                swt[t][c] = (&v.x)[e];
            }
        }
        __syncthreads();
        #pragma unroll
        for (int t = 0; t < 49; ++t)
            kreg[t] = *(const u64*)(&swt[t][2 * tx]);
    }

    // 7 rolling accumulators (static slots), f32x2 x NQ.
    // NO init needed: every slot's first write is the overwriting i==6 MUL.
    u64 acc[7][2];

    const int qOut = qbase + ty * NQ;
    int outOff = ((b * H_ + p0) * W_ + qOut) * C_ + c0;

    // ---- macros 0..6 (rows 0..13), peeled: custom waits + wedge pruning ----
    MACRO7(0, 6, 0,  1, 5, 0,  5, 6, 2);   // rows  0, 1 (wait2: Gp0 landed)
    MACRO7(2, 4, 0,  3, 3, 0,  0, 1, 2);   // rows  2, 3 (wait2: Gp1 landed)
    MACRO7(4, 2, 0,  5, 1, 0,  2, 3, 1);   // rows  4, 5 (wait1: Gp2+G0)
    MACRO7(6, 0, 1,  0, 0, 1,  4, 5, 1);   // rows  6, 7
    MACRO7(1, 0, 1,  2, 0, 1,  6, 0, 1);   // rows  8, 9
    MACRO7(3, 0, 1,  4, 0, 1,  1, 2, 1);   // rows 10,11
    MACRO7(5, 0, 1,  6, 0, 1,  3, 4, 1);   // rows 12,13

    // ---- macros 7..27 (rows 14..55): 3 x 7-macro group, I$-resident ----
    #pragma unroll 1
    for (int o = 0; o < 3; ++o) {
        GROUP7C();
    }

    // ---- tail: rows 56..61, wedge-pruned (i <= 61-t); row 61 in stage 7.
    // i == 6 excluded: fresh slots never written, and never read again. ----
    CP_WAIT(0);
    __syncthreads();
    STEP_C(0, 0, 5, 0, 1);
    STEP_C(1, 0, 4, 1, 1);
    STEP_C(2, 0, 3, 2, 1);
    STEP_C(3, 0, 2, 3, 1);
    STEP_C(4, 0, 1, 4, 1);
    STEP_C(5, 0, 0, 7, 1);
}

extern "C" void kernel_launch(void* const* d_in, const int* in_sizes, int n_in,
                              void* d_out, int out_size) {
    const float* x    = (const float*)d_in[0];   // (8,224,224,192) fp32
    const float* kern = (const float*)d_in[1];   // (192,7,7) fp32
    float* out        = (float*)d_out;           // (8,224,224,192) fp32

    dim3 grid(W_ / QT, H_ / RH, B_ * 3);  // 28 x 4 x 24 = 2688 blocks
    dim3 block(PAIRS, QTH, 1);            // 128 threads
    dwconv_pipe11<<<grid, block>>>(x, kern, out);
}

// round 17
// speedup vs baseline: 1.0102x; 1.0102x over previous
#include <cuda_runtime.h>
#include <cstdint>

#define B_  8
#define H_  224
#define W_  224
#define C_  192
#define QT  8        // q positions per block
#define NQ  2        // q per thread
#define PAIRS 32     // channel pairs (threadIdx.x)
#define QTH  4       // q-thread groups (threadIdx.y)
#define NTHREADS 128
#define RH  56       // output rows per block
#define SROW 14      // staged columns per row (QT + 6)
#define STAGES 8
#define STAGE_BYTES (SROW * 64 * 4)          // 3584 B per stage
#define RING_BYTES  (STAGES * STAGE_BYTES)   // 28672 B
#define ROWSZ (W_ * C_)
#define IMGSZ (H_ * W_ * C_)

typedef unsigned long long u64;

__device__ __forceinline__ void fma2(u64 &d, u64 a, u64 b) {
    asm("fma.rn.f32x2 %0, %1, %2, %0;" : "+l"(d) : "l"(a), "l"(b));
}
__device__ __forceinline__ void mul2(u64 &d, u64 a, u64 b) {
    asm("mul.rn.f32x2 %0, %1, %2;" : "=l"(d) : "l"(a), "l"(b));
}
__device__ __forceinline__ void cpasync16(uint32_t dst, const float* src) {
    asm volatile("cp.async.cg.shared.global [%0], [%1], 16;" :: "r"(dst), "l"(src));
}
__device__ __forceinline__ void cp_commit() {
    asm volatile("cp.async.commit_group;" ::: "memory");
}
__device__ __forceinline__ void cp_wait2() {
    asm volatile("cp.async.wait_group 2;" ::: "memory");
}
__device__ __forceinline__ void cp_wait0() {
    asm volatile("cp.async.wait_group 0;" ::: "memory");
}
__device__ __forceinline__ uint32_t smem_u32(const void* p) {
    uint32_t a;
    asm("{ .reg .u64 t; cvta.to.shared.u64 t, %1; cvt.u32.u64 %0, t; }" : "=r"(a) : "l"(p));
    return a;
}

// Compute half-step at row phase T7 (t % 7), stage byte offset SOFF.
// Kernel rows i in [ILO, IHI] only (wedge pruning).
// i == 6 is the FIRST contribution to fresh slot (T7+1)%7: emitted as an
// overwriting MUL, so no accumulator zeroing/init exists anywhere.
// Slot (T7+2)%7 completes with i == 0 and is stored (if DOSTORE).
#define STEP_RANGE(T7, ILO, IHI, SOFF, DOSTORE) do {                          \
    const char* sb = (const char*)sbuf + (SOFF) + ty * (NQ * 256) + tx * 8;   \
    u64 w[8];                                                                 \
    _Pragma("unroll")                                                         \
    for (int d = 0; d < 8; ++d)                                               \
        w[d] = *(const u64*)(sb + d * 256);                                   \
    _Pragma("unroll")                                                         \
    for (int i = 0; i < 7; ++i) {                                             \
        if (i >= (ILO) && i <= (IHI)) {                                       \
            const int s = ((T7) + i + 2) % 7;                                 \
            if (i == 6) {                                                     \
                mul2(acc[s][0], kreg[6 * 7 + 0], w[6]);                       \
                mul2(acc[s][1], kreg[6 * 7 + 0], w[7]);                       \
                _Pragma("unroll")                                             \
                for (int j = 1; j < 7; ++j) {                                 \
                    const u64 kv = kreg[6 * 7 + j];                           \
                    fma2(acc[s][0], kv, w[6 - j]);                            \
                    fma2(acc[s][1], kv, w[7 - j]);                            \
                }                                                             \
            } else {                                                          \
                _Pragma("unroll")                                             \
                for (int j = 0; j < 7; ++j) {                                 \
                    const u64 kv = kreg[i * 7 + j];                           \
                    fma2(acc[s][0], kv, w[6 - j]);                            \
                    fma2(acc[s][1], kv, w[7 - j]);                            \
                }                                                             \
            }                                                                 \
        }                                                                     \
    }                                                                         \
    if (DOSTORE) {                                                            \
        const int so = ((T7) + 2) % 7;                                        \
        *(u64*)(out + outOff)      = acc[so][0];                              \
        *(u64*)(out + outOff + C_) = acc[so][1];                              \
        outOff += ROWSZ;                                                      \
    }                                                                         \
} while (0)

// Macro step: one wait + one barrier + one commit group for TWO rows.
#define MACRO2R(T7a, LOa, T7b, LOb, DOSTORE) do {                             \
    cp_wait2();                                                               \
    __syncthreads();                                                          \
    {                                                                         \
        const uint32_t dA = sdst + offP;                                      \
        cpasync16(dA, rowPtr + colOff0);                                      \
        if (has1) cpasync16(dA + 2048, rowPtr + colOff1);                     \
        rowPtr += ROWSZ; if (rowPtr >= xEnd) rowPtr -= IMGSZ;                 \
        uint32_t p2 = offP + STAGE_BYTES;                                     \
        if (p2 >= RING_BYTES) p2 -= RING_BYTES;                               \
        const uint32_t dB = sdst + p2;                                        \
        cpasync16(dB, rowPtr + colOff0);                                      \
        if (has1) cpasync16(dB + 2048, rowPtr + colOff1);                     \
        rowPtr += ROWSZ; if (rowPtr >= xEnd) rowPtr -= IMGSZ;                 \
        cp_commit();                                                          \
        offP += 2 * STAGE_BYTES; if (offP >= RING_BYTES) offP -= RING_BYTES;  \
    }                                                                         \
    STEP_RANGE(T7a, LOa, 6, offCa, DOSTORE);                                  \
    offCa += 2 * STAGE_BYTES; if (offCa >= RING_BYTES) offCa -= RING_BYTES;   \
    STEP_RANGE(T7b, LOb, 6, offCb, DOSTORE);                                  \
    offCb += 2 * STAGE_BYTES; if (offCb >= RING_BYTES) offCb -= RING_BYTES;   \
} while (0)

// 7 macro steps = 14 rows (acc phase period). Starts at t%7 == 6.
#define GROUP7M()                                                             \
    MACRO2R(6, 0, 0, 0, 1); MACRO2R(1, 0, 2, 0, 1); MACRO2R(3, 0, 4, 0, 1);   \
    MACRO2R(5, 0, 6, 0, 1); MACRO2R(0, 0, 1, 0, 1); MACRO2R(2, 0, 3, 0, 1);   \
    MACRO2R(4, 0, 5, 0, 1)

// Tail steps exclude i == 6: fresh slots never written -- and never read.
#define TAILSTEP(T7, IHI, CUR) do {                                           \
    STEP_RANGE(T7, 0, IHI, CUR, 1);                                           \
    CUR += 2 * STAGE_BYTES; if (CUR >= RING_BYTES) CUR -= RING_BYTES;         \
} while (0)

__global__ void __launch_bounds__(NTHREADS, 3)
dwconv_final(const float* __restrict__ x, const float* __restrict__ kern,
             float* __restrict__ out)
{
    __shared__ float sbuf[STAGES][SROW][64];   // 28,672 B input ring
    __shared__ float swt[49][64];              // 12,544 B weight transpose buf

    const int tx  = threadIdx.x;           // channel pair 0..31
    const int ty  = threadIdx.y;           // q group 0..3
    const int tid = ty * PAIRS + tx;

    const int wt = blockIdx.x;              // 0..27
    const int ht = blockIdx.y;              // 0..3
    const int bz = blockIdx.z;              // 0..23
    const int b  = bz / 3;
    const int g  = bz % 3;

    const int qbase = wt * QT;
    const int p0    = ht * RH;              // p0 % 7 == 0
    const int cbase = g * 64;
    const int c0    = cbase + 2 * tx;

    // ---- cp.async staging plan: 224 float4 per stage, threads 0..95 take 2 ----
    const int s0 = tid >> 4, v0 = tid & 15;             // cols 0..7
    const bool has1 = tid < 96;
    const int s1 = (tid + 128) >> 4;                    // cols 8..13
    int qg0 = qbase - 3 + s0; qg0 += (qg0 < 0) ? W_ : 0; qg0 -= (qg0 >= W_) ? W_ : 0;
    int qg1 = qbase - 3 + s1; qg1 += (qg1 < 0) ? W_ : 0; qg1 -= (qg1 >= W_) ? W_ : 0;
    const int colOff0 = qg0 * C_ + cbase + v0 * 4;
    const int colOff1 = qg1 * C_ + cbase + v0 * 4;
    const uint32_t sdst = smem_u32(&sbuf[0][0][0]) + (uint32_t)(s0 * 256 + v0 * 16);

    // row cursor (circular over H, pointer-only)
    const float* const xBase = x + b * IMGSZ;
    const float* const xEnd  = xBase + IMGSZ;
    const float* rowPtr = xBase + (p0 - 3 < 0 ? p0 - 3 + H_ : p0 - 3) * ROWSZ;

    // ---- FIRST: launch prologue cp.asyncs (rows 0..5 -> stages 0..5) so the
    // DRAM latency of the first rows overlaps the weight load below ----
    #pragma unroll
    for (int pr = 0; pr < 3; ++pr) {
        uint32_t dA = sdst + (2 * pr) * STAGE_BYTES;
        cpasync16(dA, rowPtr + colOff0);
        if (has1) cpasync16(dA + 2048, rowPtr + colOff1);
        rowPtr += ROWSZ; if (rowPtr >= xEnd) rowPtr -= IMGSZ;
        uint32_t dB = sdst + (2 * pr + 1) * STAGE_BYTES;
        cpasync16(dB, rowPtr + colOff0);
        if (has1) cpasync16(dB + 2048, rowPtr + colOff1);
        rowPtr += ROWSZ; if (rowPtr >= xEnd) rowPtr -= IMGSZ;
        cp_commit();
    }

    // ---- weight load (overlapped with prologue flight): coalesced LDG of the
    // 64-ch slab as 784 float4 -> transpose into swt[t][c] -> LDS.64 taps ----
    u64 kreg[49];
    {
        const float4* kslab = (const float4*)(kern + cbase * 49);  // 16B-aligned
        #pragma unroll
        for (int i = tid; i < 784; i += NTHREADS) {
            const float4 v = kslab[i];
            const int base = i * 4;             // = c*49 + t
            #pragma unroll
            for (int e = 0; e < 4; ++e) {
                const int idx = base + e;
                const int c = idx / 49;
                const int t = idx - c * 49;
                swt[t][c] = (&v.x)[e];
            }
        }
        __syncthreads();
        #pragma unroll
        for (int t = 0; t < 49; ++t)
            kreg[t] = *(const u64*)(&swt[t][2 * tx]);
    }

    uint32_t offCa = 0;
    uint32_t offCb = STAGE_BYTES;
    uint32_t offP  = 6 * STAGE_BYTES;

    // 7 rolling accumulators (static slots), f32x2 x NQ.
    // NO init: every slot's first write is the overwriting i==6 MUL.
    u64 acc[7][2];

    const int qOut = qbase + ty * NQ;
    int outOff = ((b * H_ + p0) * W_ + qOut) * C_ + c0;

    // ---- warm-up: rows t = 0..5, wedge-pruned (i >= 6-t), no stores ----
    MACRO2R(0, 6, 1, 5, 0);
    MACRO2R(2, 4, 3, 3, 0);
    MACRO2R(4, 2, 5, 1, 0);

    // ---- main: rows t = 6..47, three 7-macro groups (I$-resident) ----
    #pragma unroll 1
    for (int o = 0; o < 3; ++o) {
        GROUP7M();
    }
    // ---- main remainder: rows t = 48..55 ----
    MACRO2R(6, 0, 0, 0, 1);
    MACRO2R(1, 0, 2, 0, 1);
    MACRO2R(3, 0, 4, 0, 1);
    MACRO2R(5, 0, 6, 0, 1);

    // ---- tail: rows t = 56..61, wedge-pruned (i <= 61-t), all data staged ----
    cp_wait0();
    __syncthreads();
    TAILSTEP(0, 5, offCa);
    TAILSTEP(1, 4, offCb);
    TAILSTEP(2, 3, offCa);
    TAILSTEP(3, 2, offCb);
    TAILSTEP(4, 1, offCa);
    TAILSTEP(5, 0, offCb);
}

extern "C" void kernel_launch(void* const* d_in, const int* in_sizes, int n_in,
                              void* d_out, int out_size) {
    const float* x    = (const float*)d_in[0];   // (8,224,224,192) fp32
    const float* kern = (const float*)d_in[1];   // (192,7,7) fp32
    float* out        = (float*)d_out;           // (8,224,224,192) fp32

    dim3 grid(W_ / QT, H_ / RH, B_ * 3);  // 28 x 4 x 24 = 2688 blocks
    dim3 block(PAIRS, QTH, 1);            // 128 threads
    dwconv_final<<<grid, block>>>(x, kern, out);
}